// round 5
// baseline (speedup 1.0000x reference)
#include <cuda_runtime.h>
#include <math.h>

#define H    2048
#define TPB  256
#define NWARP (TPB / 32)
#define L    3
#define NQ   4                 // counter shards (one per j-quarter)
#define JQ   (H / NQ)          // 512 js per quarter
#define NBLK 888               // 6 blocks/SM * 148 SMs = one full wave
#define BPQ  (NBLK / NQ)       // 222 blocks per quarter

// Inter-layer hidden state ping-pong
__device__ __align__(16) float g_hbuf[2][H];

// Work-stealing counters: [layer][quarter], padded to 128B so each lands in a
// different L2 slice. Reset in-kernel each use -> graph-replay-safe.
__device__ unsigned g_ctr[L][NQ][32];

__device__ __forceinline__ float dot4(float4 w, float4 v) {
    return w.x * v.x + w.y * v.y + w.z * v.z + w.w * v.w;
}

__device__ __forceinline__ float sigmoidf_(float v) {
    return 1.0f / (1.0f + __expf(-v));
}

// One kernel per layer. 888 blocks; block steals output elements j from its
// quarter's counter. Inner body identical to the proven R1 kernel:
// thread-strided float4 loads over all 8 gate rows, 4 accumulators.
__global__ void __launch_bounds__(TPB, 6) lstm_layer_ws_kernel(
    const float* __restrict__ Wi,   // [4H, H]
    const float* __restrict__ Wh,   // [4H, H]
    const float* __restrict__ bi,   // [4H]
    const float* __restrict__ bh,   // [4H]
    const float* __restrict__ xin,  // [H]
    const float* __restrict__ hin,  // [H]
    const float* __restrict__ cin,  // [H]
    float* __restrict__ hout,       // [H]
    unsigned* __restrict__ ctr)     // [NQ][32]
{
    const int t    = threadIdx.x;
    const int warp = t >> 5;
    const int lane = t & 31;
    const int q    = blockIdx.x & (NQ - 1);
    unsigned* myctr = ctr + q * 32;
    const int jbase = q * JQ;

    const float4* __restrict__ x4 = (const float4*)xin;
    const float4* __restrict__ h4 = (const float4*)hin;

    __shared__ int   sj;
    __shared__ float s[4][NWARP];

    #pragma unroll 1
    while (true) {
        if (t == 0) sj = (int)atomicAdd(myctr, 1u);
        __syncthreads();
        const int jq = sj;
        if (jq >= JQ) {
            // Last overflow fetch in this quarter resets the counter for the
            // next graph replay (value JQ + BPQ - 1 is the final increment).
            if (t == 0 && jq == JQ + BPQ - 1) atomicExch(myctr, 0u);
            break;
        }
        const int j = jbase + jq;

        const float4* __restrict__ wi0 = (const float4*)(Wi + (size_t)(0 * H + j) * H);
        const float4* __restrict__ wi1 = (const float4*)(Wi + (size_t)(1 * H + j) * H);
        const float4* __restrict__ wi2 = (const float4*)(Wi + (size_t)(2 * H + j) * H);
        const float4* __restrict__ wi3 = (const float4*)(Wi + (size_t)(3 * H + j) * H);
        const float4* __restrict__ wh0 = (const float4*)(Wh + (size_t)(0 * H + j) * H);
        const float4* __restrict__ wh1 = (const float4*)(Wh + (size_t)(1 * H + j) * H);
        const float4* __restrict__ wh2 = (const float4*)(Wh + (size_t)(2 * H + j) * H);
        const float4* __restrict__ wh3 = (const float4*)(Wh + (size_t)(3 * H + j) * H);

        float a0 = 0.f, a1 = 0.f, a2 = 0.f, a3 = 0.f;
        #pragma unroll
        for (int k = t; k < H / 4; k += TPB) {
            float4 xv = x4[k];
            float4 hv = h4[k];
            a0 += dot4(wi0[k], xv);
            a1 += dot4(wi1[k], xv);
            a2 += dot4(wi2[k], xv);
            a3 += dot4(wi3[k], xv);
            a0 += dot4(wh0[k], hv);
            a1 += dot4(wh1[k], hv);
            a2 += dot4(wh2[k], hv);
            a3 += dot4(wh3[k], hv);
        }

        #pragma unroll
        for (int off = 16; off > 0; off >>= 1) {
            a0 += __shfl_xor_sync(0xffffffffu, a0, off);
            a1 += __shfl_xor_sync(0xffffffffu, a1, off);
            a2 += __shfl_xor_sync(0xffffffffu, a2, off);
            a3 += __shfl_xor_sync(0xffffffffu, a3, off);
        }
        if (lane == 0) {
            s[0][warp] = a0;
            s[1][warp] = a1;
            s[2][warp] = a2;
            s[3][warp] = a3;
        }
        __syncthreads();

        if (t == 0) {
            float gi = 0.f, gf = 0.f, gg = 0.f, go = 0.f;
            #pragma unroll
            for (int w = 0; w < NWARP; w++) {
                gi += s[0][w]; gf += s[1][w];
                gg += s[2][w]; go += s[3][w];
            }
            gi += bi[0 * H + j] + bh[0 * H + j];
            gf += bi[1 * H + j] + bh[1 * H + j];
            gg += bi[2 * H + j] + bh[2 * H + j];
            go += bi[3 * H + j] + bh[3 * H + j];

            float iv = sigmoidf_(gi);
            float fv = sigmoidf_(gf);
            float gv = tanhf(gg);
            float ov = sigmoidf_(go);
            float c_new = fv * cin[j] + iv * gv;
            hout[j] = ov * tanhf(c_new);
        }
        __syncthreads();  // protect s[][] and sj before next steal
    }
}

extern "C" void kernel_launch(void* const* d_in, const int* in_sizes, int n_in,
                              void* d_out, int out_size) {
    (void)in_sizes; (void)n_in; (void)out_size;
    const float* x    = (const float*)d_in[0];  // [H]
    const float* W_ih = (const float*)d_in[1];  // [L, 4H, H]
    const float* W_hh = (const float*)d_in[2];  // [L, 4H, H]
    const float* b_ih = (const float*)d_in[3];  // [L, 4H]
    const float* b_hh = (const float*)d_in[4];  // [L, 4H]
    const float* h0   = (const float*)d_in[5];  // [L, H]
    const float* c0   = (const float*)d_in[6];  // [L, H]
    float* out = (float*)d_out;                 // [H]

    float* hbuf;
    cudaGetSymbolAddress((void**)&hbuf, g_hbuf);
    float* hbuf0 = hbuf;
    float* hbuf1 = hbuf + H;

    unsigned* ctr;
    cudaGetSymbolAddress((void**)&ctr, g_ctr);

    const size_t Wstride = (size_t)4 * H * H;
    const size_t bstride = (size_t)4 * H;
    const size_t cstride = (size_t)NQ * 32;

    lstm_layer_ws_kernel<<<NBLK, TPB>>>(W_ih, W_hh, b_ih, b_hh,
                                        x, h0, c0, hbuf0, ctr);
    lstm_layer_ws_kernel<<<NBLK, TPB>>>(W_ih + Wstride, W_hh + Wstride,
                                        b_ih + bstride, b_hh + bstride,
                                        hbuf0, h0 + H, c0 + H, hbuf1,
                                        ctr + cstride);
    lstm_layer_ws_kernel<<<NBLK, TPB>>>(W_ih + 2 * Wstride, W_hh + 2 * Wstride,
                                        b_ih + 2 * bstride, b_hh + 2 * bstride,
                                        hbuf1, h0 + 2 * H, c0 + 2 * H, out,
                                        ctr + 2 * cstride);
}

// round 6
// speedup vs baseline: 1.3841x; 1.3841x over previous
#include <cuda_runtime.h>
#include <math.h>

#define H    2048
#define TPB  256
#define NWARP (TPB / 32)
#define L    3

// Inter-layer hidden state
__device__ __align__(16) float g_hbuf[2][H];
// Precomputed P[l-1][gate][j] = (Wh_l @ h0_l)[gate*H+j] + bi + bh, layers 1,2
__device__ __align__(16) float g_P[2][4][H];

__device__ __forceinline__ float dot4(float4 w, float4 v) {
    return w.x * v.x + w.y * v.y + w.z * v.z + w.w * v.w;
}
__device__ __forceinline__ float sigmoidf_(float v) {
    return 1.0f / (1.0f + __expf(-v));
}

// ---------------------------------------------------------------------------
// Kernel 1: grid = 6144.
//   blocks [0,2048):     full layer-0 cell (8 rows: Wi@x + Wh@h0, epilogue) -> g_hbuf[0]
//   blocks [2048,4096):  P for layer 1 (4 Wh rows @ h0[1] + biases)         -> g_P[0]
//   blocks [4096,6144):  P for layer 2                                      -> g_P[1]
// Everything here depends only on kernel inputs -> fully parallel, 6.92 waves
// at 6 blocks/SM with a 92%-full final wave.
// ---------------------------------------------------------------------------
__global__ void __launch_bounds__(TPB) lstm_k1(
    const float* __restrict__ x,     // [H]
    const float* __restrict__ W_ih,  // [L, 4H, H]
    const float* __restrict__ W_hh,  // [L, 4H, H]
    const float* __restrict__ b_ih,  // [L, 4H]
    const float* __restrict__ b_hh,  // [L, 4H]
    const float* __restrict__ h0,    // [L, H]
    const float* __restrict__ c0)    // [L, H]
{
    const int b    = blockIdx.x;
    const int t    = threadIdx.x;
    const int warp = t >> 5;
    const int lane = t & 31;

    __shared__ float s[4][NWARP];

    if (b < H) {
        // ---- Full layer-0 cell for output element j = b (R1 body) ----
        const int j = b;
        const float* Wi = W_ih;
        const float* Wh = W_hh;
        const float4* __restrict__ x4 = (const float4*)x;
        const float4* __restrict__ h4 = (const float4*)h0;

        const float4* __restrict__ wi0 = (const float4*)(Wi + (size_t)(0 * H + j) * H);
        const float4* __restrict__ wi1 = (const float4*)(Wi + (size_t)(1 * H + j) * H);
        const float4* __restrict__ wi2 = (const float4*)(Wi + (size_t)(2 * H + j) * H);
        const float4* __restrict__ wi3 = (const float4*)(Wi + (size_t)(3 * H + j) * H);
        const float4* __restrict__ wh0 = (const float4*)(Wh + (size_t)(0 * H + j) * H);
        const float4* __restrict__ wh1 = (const float4*)(Wh + (size_t)(1 * H + j) * H);
        const float4* __restrict__ wh2 = (const float4*)(Wh + (size_t)(2 * H + j) * H);
        const float4* __restrict__ wh3 = (const float4*)(Wh + (size_t)(3 * H + j) * H);

        float a0 = 0.f, a1 = 0.f, a2 = 0.f, a3 = 0.f;
        #pragma unroll
        for (int k = t; k < H / 4; k += TPB) {
            float4 xv = x4[k];
            float4 hv = h4[k];
            a0 += dot4(wi0[k], xv);
            a1 += dot4(wi1[k], xv);
            a2 += dot4(wi2[k], xv);
            a3 += dot4(wi3[k], xv);
            a0 += dot4(wh0[k], hv);
            a1 += dot4(wh1[k], hv);
            a2 += dot4(wh2[k], hv);
            a3 += dot4(wh3[k], hv);
        }
        #pragma unroll
        for (int off = 16; off > 0; off >>= 1) {
            a0 += __shfl_xor_sync(0xffffffffu, a0, off);
            a1 += __shfl_xor_sync(0xffffffffu, a1, off);
            a2 += __shfl_xor_sync(0xffffffffu, a2, off);
            a3 += __shfl_xor_sync(0xffffffffu, a3, off);
        }
        if (lane == 0) { s[0][warp] = a0; s[1][warp] = a1; s[2][warp] = a2; s[3][warp] = a3; }
        __syncthreads();
        if (t == 0) {
            float gi = 0.f, gf = 0.f, gg = 0.f, go = 0.f;
            #pragma unroll
            for (int w = 0; w < NWARP; w++) {
                gi += s[0][w]; gf += s[1][w]; gg += s[2][w]; go += s[3][w];
            }
            gi += b_ih[0 * H + j] + b_hh[0 * H + j];
            gf += b_ih[1 * H + j] + b_hh[1 * H + j];
            gg += b_ih[2 * H + j] + b_hh[2 * H + j];
            go += b_ih[3 * H + j] + b_hh[3 * H + j];
            float iv = sigmoidf_(gi);
            float fv = sigmoidf_(gf);
            float gv = tanhf(gg);
            float ov = sigmoidf_(go);
            float c_new = fv * c0[j] + iv * gv;
            g_hbuf[0][j] = ov * tanhf(c_new);
        }
    } else {
        // ---- P precompute: layer l in {1,2}, output element j ----
        const int bb = b - H;
        const int l  = 1 + (bb >> 11);         // bb / 2048
        const int j  = bb & (H - 1);
        const float* Wh = W_hh + (size_t)l * 4 * H * H;
        const float* bi = b_ih + l * 4 * H;
        const float* bh = b_hh + l * 4 * H;
        const float4* __restrict__ h4 = (const float4*)(h0 + l * H);

        const float4* __restrict__ r0 = (const float4*)(Wh + (size_t)(0 * H + j) * H);
        const float4* __restrict__ r1 = (const float4*)(Wh + (size_t)(1 * H + j) * H);
        const float4* __restrict__ r2 = (const float4*)(Wh + (size_t)(2 * H + j) * H);
        const float4* __restrict__ r3 = (const float4*)(Wh + (size_t)(3 * H + j) * H);

        float a0 = 0.f, a1 = 0.f, a2 = 0.f, a3 = 0.f;
        #pragma unroll
        for (int k = t; k < H / 4; k += TPB) {
            float4 hv = h4[k];
            a0 += dot4(r0[k], hv);
            a1 += dot4(r1[k], hv);
            a2 += dot4(r2[k], hv);
            a3 += dot4(r3[k], hv);
        }
        #pragma unroll
        for (int off = 16; off > 0; off >>= 1) {
            a0 += __shfl_xor_sync(0xffffffffu, a0, off);
            a1 += __shfl_xor_sync(0xffffffffu, a1, off);
            a2 += __shfl_xor_sync(0xffffffffu, a2, off);
            a3 += __shfl_xor_sync(0xffffffffu, a3, off);
        }
        if (lane == 0) { s[0][warp] = a0; s[1][warp] = a1; s[2][warp] = a2; s[3][warp] = a3; }
        __syncthreads();
        if (t == 0) {
            float p0 = 0.f, p1 = 0.f, p2 = 0.f, p3 = 0.f;
            #pragma unroll
            for (int w = 0; w < NWARP; w++) {
                p0 += s[0][w]; p1 += s[1][w]; p2 += s[2][w]; p3 += s[3][w];
            }
            g_P[l - 1][0][j] = p0 + bi[0 * H + j] + bh[0 * H + j];
            g_P[l - 1][1][j] = p1 + bi[1 * H + j] + bh[1 * H + j];
            g_P[l - 1][2][j] = p2 + bi[2 * H + j] + bh[2 * H + j];
            g_P[l - 1][3][j] = p3 + bi[3 * H + j] + bh[3 * H + j];
        }
    }
}

// ---------------------------------------------------------------------------
// Kernels 2,3: layer l = 1 or 2. Only Wi_l @ x_l remains (4 rows per j) plus
// precomputed P and epilogue. Half the rows of R1 -> ~30 regs, 8 blocks/SM.
// ---------------------------------------------------------------------------
__global__ void __launch_bounds__(TPB, 8) lstm_wi_kernel(
    const float* __restrict__ Wi,    // [4H, H] layer l
    const float* __restrict__ xin,   // [H] = h of previous layer
    const float* __restrict__ cin,   // [H] = c0[l]
    const float* __restrict__ P,     // [4][H] precomputed
    float* __restrict__ hout)        // [H]
{
    const int j    = blockIdx.x;
    const int t    = threadIdx.x;
    const int warp = t >> 5;
    const int lane = t & 31;

    const float4* __restrict__ x4 = (const float4*)xin;
    const float4* __restrict__ r0 = (const float4*)(Wi + (size_t)(0 * H + j) * H);
    const float4* __restrict__ r1 = (const float4*)(Wi + (size_t)(1 * H + j) * H);
    const float4* __restrict__ r2 = (const float4*)(Wi + (size_t)(2 * H + j) * H);
    const float4* __restrict__ r3 = (const float4*)(Wi + (size_t)(3 * H + j) * H);

    float a0 = 0.f, a1 = 0.f, a2 = 0.f, a3 = 0.f;
    #pragma unroll
    for (int k = t; k < H / 4; k += TPB) {
        float4 xv = x4[k];
        a0 += dot4(r0[k], xv);
        a1 += dot4(r1[k], xv);
        a2 += dot4(r2[k], xv);
        a3 += dot4(r3[k], xv);
    }
    #pragma unroll
    for (int off = 16; off > 0; off >>= 1) {
        a0 += __shfl_xor_sync(0xffffffffu, a0, off);
        a1 += __shfl_xor_sync(0xffffffffu, a1, off);
        a2 += __shfl_xor_sync(0xffffffffu, a2, off);
        a3 += __shfl_xor_sync(0xffffffffu, a3, off);
    }

    __shared__ float s[4][NWARP];
    if (lane == 0) { s[0][warp] = a0; s[1][warp] = a1; s[2][warp] = a2; s[3][warp] = a3; }
    __syncthreads();

    if (t == 0) {
        float gi = 0.f, gf = 0.f, gg = 0.f, go = 0.f;
        #pragma unroll
        for (int w = 0; w < NWARP; w++) {
            gi += s[0][w]; gf += s[1][w]; gg += s[2][w]; go += s[3][w];
        }
        gi += P[0 * H + j];
        gf += P[1 * H + j];
        gg += P[2 * H + j];
        go += P[3 * H + j];
        float iv = sigmoidf_(gi);
        float fv = sigmoidf_(gf);
        float gv = tanhf(gg);
        float ov = sigmoidf_(go);
        float c_new = fv * cin[j] + iv * gv;
        hout[j] = ov * tanhf(c_new);
    }
}

extern "C" void kernel_launch(void* const* d_in, const int* in_sizes, int n_in,
                              void* d_out, int out_size) {
    (void)in_sizes; (void)n_in; (void)out_size;
    const float* x    = (const float*)d_in[0];
    const float* W_ih = (const float*)d_in[1];
    const float* W_hh = (const float*)d_in[2];
    const float* b_ih = (const float*)d_in[3];
    const float* b_hh = (const float*)d_in[4];
    const float* h0   = (const float*)d_in[5];
    const float* c0   = (const float*)d_in[6];
    float* out = (float*)d_out;

    float* hbuf;
    cudaGetSymbolAddress((void**)&hbuf, g_hbuf);
    float* P;
    cudaGetSymbolAddress((void**)&P, g_P);

    const size_t Wstride = (size_t)4 * H * H;

    // K1: layer-0 complete + P for layers 1,2 (fully input-parallel, 268 MB)
    lstm_k1<<<3 * H, TPB>>>(x, W_ih, W_hh, b_ih, b_hh, h0, c0);
    // K2: layer 1 = Wi_1 @ h1 + P_1, epilogue
    lstm_wi_kernel<<<H, TPB>>>(W_ih + Wstride, hbuf, c0 + H,
                               P, hbuf + H);
    // K3: layer 2 = Wi_2 @ h2 + P_2, epilogue -> out
    lstm_wi_kernel<<<H, TPB>>>(W_ih + 2 * Wstride, hbuf + H, c0 + 2 * H,
                               P + 4 * H, out);
}